// round 12
// baseline (speedup 1.0000x reference)
#include <cuda_runtime.h>
#include <cuda_fp16.h>
#include <mma.h>

using namespace nvcuda;

#define NN 500000
#define EE 2000000
#define GG 64
#define EPS 1e-5f
#define SCAN_B 512
#define NBS ((NN + SCAN_B - 1) / SCAN_B)   // 977
#define NBD ((EE + 255) / 256)             // 7813

// ---------------- scratch (device globals; no allocs allowed) ----------------
__device__ __align__(16) int    g_deg[NN];
__device__ __align__(16) float  g_dis[NN];
__device__ __align__(16) int2   g_dc[NN];          // {dis bits, combo}
__device__ __align__(16) int    g_off[NN + 1];
__device__ __align__(16) int    g_cur[NN];
__device__ __align__(16) int    g_bsum[NBS];
__device__ __align__(16) int    g_srcs[EE];
__device__ __align__(16) float  g_S[NN * 9];
__device__ __align__(16) __half g_y1[((size_t)NN + 128) * 64];  // dis*(z1@W2) fp16
__device__ __align__(16) __half g_y[(size_t)NN * 64];           // aggregated layer-2 out
__device__ __align__(16) float  g_M1[9 * 64];
__device__ __align__(16) float  g_mom[64];
__device__ __align__(16) float  g_s2[64];
__device__ __align__(16) float  g_q2[64];
__device__ __align__(16) float  g_psum[GG * 64];
__device__ __align__(16) int    g_pmax[GG * 64];
__device__ __align__(16) int    g_pmin[GG * 64];
__device__                int    g_cnt[GG];

// ---------------- helpers ----------------
__device__ __forceinline__ void atomicMaxFloat(int* addr, float v) {
    if (v >= 0.0f) atomicMax(addr, __float_as_int(v));
    else           atomicMin((unsigned int*)addr, __float_as_uint(v));
}
__device__ __forceinline__ void atomicMinFloat(int* addr, float v) {
    if (v >= 0.0f) atomicMin(addr, __float_as_int(v));
    else           atomicMax((unsigned int*)addr, __float_as_uint(v));
}
__device__ __forceinline__ void acc8(float* a, uint4 r) {
    float2 q0 = __half22float2(*(half2*)&r.x);
    float2 q1 = __half22float2(*(half2*)&r.y);
    float2 q2 = __half22float2(*(half2*)&r.z);
    float2 q3 = __half22float2(*(half2*)&r.w);
    a[0] += q0.x; a[1] += q0.y; a[2] += q1.x; a[3] += q1.y;
    a[4] += q2.x; a[5] += q2.y; a[6] += q3.x; a[7] += q3.y;
}

// ======= kernel 1: degree histogram + all small init + cnt + M1 prep =========
__global__ void k_init_deg(const int* __restrict__ edst,
                           const int* __restrict__ batch,
                           const float* __restrict__ emb_type,
                           const float* __restrict__ emb_inv,
                           const float* __restrict__ W1) {
    int b = blockIdx.x;
    int tid = threadIdx.x;
    if (b < NBD) {
        int e = b * 256 + tid;
        if (e < EE) atomicAdd(&g_deg[edst[e]], 1);
        return;
    }
    int extra = b - NBD;
    if (extra == 0) {
        for (int i = tid; i < GG * 64; i += 256) {
            g_pmax[i] = 0xFF800000;
            g_pmin[i] = 0x7F800000;
            g_psum[i] = 0.0f;
        }
        if (tid < 64) { g_mom[tid] = 0.0f; g_s2[tid] = 0.0f; g_q2[tid] = 0.0f; }
    } else if (extra == 1) {
        int g = tid;
        if (g < GG) {
            int lo0 = 0, hi0 = NN;
            while (lo0 < hi0) { int m = (lo0 + hi0) >> 1; if (batch[m] < g) lo0 = m + 1; else hi0 = m; }
            int lo1 = lo0, hi1 = NN;
            while (lo1 < hi1) { int m = (lo1 + hi1) >> 1; if (batch[m] < g + 1) lo1 = m + 1; else hi1 = m; }
            g_cnt[g] = lo1 - lo0;
        }
    } else {
        for (int t = tid; t < 9 * 64; t += 256) {
            int combo = t >> 6;
            int f = t & 63;
            int ty = combo / 3, iv = combo % 3;
            float acc = 0.0f;
#pragma unroll
            for (int k = 0; k < 16; k++) {
                acc = fmaf(emb_type[ty * 16 + k], W1[k * 64 + f], acc);
                acc = fmaf(emb_inv[iv * 16 + k], W1[(16 + k) * 64 + f], acc);
            }
            g_M1[combo * 64 + f] = acc;
        }
    }
}

// ======= kernel 2: per-node dis/dc/S-row + block-scan of deg (scan stage 1) ==
__global__ __launch_bounds__(SCAN_B) void k_dis_scan1(const int* __restrict__ node_type,
                                                      const int* __restrict__ num_inv) {
    __shared__ int s[SCAN_B];
    int gid = blockIdx.x * SCAN_B + threadIdx.x;
    int dval = (gid < NN) ? g_deg[gid] : 0;
    if (gid < NN) {
        int d = dval + 1;
        float dis = rsqrtf((float)d);
        g_dis[gid] = dis;
        int c = node_type[gid] * 3 + num_inv[gid];
        g_dc[gid] = make_int2(__float_as_int(dis), c);
        float id = dis * dis;
#pragma unroll
        for (int t = 0; t < 9; t++) g_S[(size_t)gid * 9 + t] = (t == c) ? id : 0.0f;
    }
    s[threadIdx.x] = dval;
    __syncthreads();
    for (int o = 1; o < SCAN_B; o <<= 1) {
        int x = s[threadIdx.x];
        if (threadIdx.x >= o) x += s[threadIdx.x - o];
        __syncthreads();
        s[threadIdx.x] = x;
        __syncthreads();
    }
    if (threadIdx.x == SCAN_B - 1) g_bsum[blockIdx.x] = s[SCAN_B - 1];
}

// ======= kernel 3: fused scan stages 2+3 ======================================
__global__ __launch_bounds__(SCAN_B) void k_scan23() {
    __shared__ int s[SCAN_B];
    __shared__ int red[SCAN_B];
    int acc = 0;
    for (int j = threadIdx.x; j < blockIdx.x; j += SCAN_B) acc += g_bsum[j];
    red[threadIdx.x] = acc;
    __syncthreads();
    for (int o = SCAN_B / 2; o > 0; o >>= 1) {
        if ((int)threadIdx.x < o) red[threadIdx.x] += red[threadIdx.x + o];
        __syncthreads();
    }
    int bpre = red[0];

    int gid = blockIdx.x * SCAN_B + threadIdx.x;
    int dval = (gid < NN) ? g_deg[gid] : 0;
    s[threadIdx.x] = dval;
    __syncthreads();
    for (int o = 1; o < SCAN_B; o <<= 1) {
        int x = s[threadIdx.x];
        if (threadIdx.x >= o) x += s[threadIdx.x - o];
        __syncthreads();
        s[threadIdx.x] = x;
        __syncthreads();
    }
    if (gid < NN) {
        int excl = s[threadIdx.x] - dval + bpre;
        g_off[gid] = excl;
        g_cur[gid] = excl;
        if (gid == NN - 1) g_off[NN] = excl + dval;
    }
}

// ======= kernel 4: CSR ticket-scatter + layer-1 bucket aggregation ===========
__global__ void k_scatter_edge1(const int* __restrict__ esrc, const int* __restrict__ edst) {
    int e = blockIdx.x * blockDim.x + threadIdx.x;
    if (e >= EE) return;
    int s = esrc[e], d = edst[e];
    int2 ds = __ldg(&g_dc[s]);
    int2 dd = __ldg(&g_dc[d]);
    int pos = atomicAdd(&g_cur[d], 1);
    g_srcs[pos] = s;
    atomicAdd(&g_S[(size_t)d * 9 + ds.y], __int_as_float(ds.x) * __int_as_float(dd.x));
}

// ======= kernel 5: S moments ==================================================
__global__ __launch_bounds__(256) void k_stats() {
    __shared__ float sS[256 * 9];
    __shared__ float sred[8][54];
    float m[54];
#pragma unroll
    for (int i = 0; i < 54; i++) m[i] = 0.0f;

    int tiles = (NN + 255) / 256;
    for (int t = blockIdx.x; t < tiles; t += gridDim.x) {
        int base = t * 256;
        int cnt = min(256, NN - base);
        int tot = cnt * 9;
        __syncthreads();
        for (int i = threadIdx.x; i < tot; i += 256) sS[i] = g_S[(size_t)base * 9 + i];
        __syncthreads();
        if ((int)threadIdx.x < cnt) {
            float r[9];
#pragma unroll
            for (int j = 0; j < 9; j++) r[j] = sS[threadIdx.x * 9 + j];
            int k = 9;
#pragma unroll
            for (int i = 0; i < 9; i++) {
                m[i] += r[i];
#pragma unroll
                for (int j = i; j < 9; j++) { m[k] = fmaf(r[i], r[j], m[k]); k++; }
            }
        }
    }
#pragma unroll
    for (int v = 0; v < 54; v++) {
#pragma unroll
        for (int o = 16; o > 0; o >>= 1) m[v] += __shfl_down_sync(0xffffffffu, m[v], o);
    }
    int lane = threadIdx.x & 31, warp = threadIdx.x >> 5;
    if (lane == 0) {
#pragma unroll
        for (int v = 0; v < 54; v++) sred[warp][v] = m[v];
    }
    __syncthreads();
    if (threadIdx.x < 54) {
        float acc = 0.0f;
#pragma unroll
        for (int w = 0; w < 8; w++) acc += sred[w][threadIdx.x];
        atomicAdd(&g_mom[threadIdx.x], acc);
    }
}

// ======= kernel 6: fused BN1 + layer1 + wmma GEMM -> y1' fp16 ================
#define ZLD 80
__global__ __launch_bounds__(256) void k_fused1(const float* __restrict__ W2,
                                                const float* __restrict__ gamma1,
                                                const float* __restrict__ beta1) {
    __shared__ float  sM1[9 * 64];
    __shared__ float  sA[64], sSh[64];
    __shared__ __half sW[64 * 64];
    __shared__ __half sZ[128 * ZLD];

    int tid = threadIdx.x;
    for (int i = tid; i < 9 * 64; i += 256) sM1[i] = g_M1[i];
    for (int i = tid; i < 64 * 64 / 2; i += 256) {
        float2 w = ((const float2*)W2)[i];
        ((half2*)sW)[i] = __floats2half2_rn(w.x, w.y);
    }
    __syncthreads();

    if (tid < 64) {
        int f = tid;
        float mcol[9];
#pragma unroll
        for (int t = 0; t < 9; t++) mcol[t] = sM1[t * 64 + f];
        float mean = 0.0f;
#pragma unroll
        for (int t = 0; t < 9; t++) mean = fmaf(g_mom[t], mcol[t], mean);
        mean /= (float)NN;
        float e2 = 0.0f;
        int k = 9;
#pragma unroll
        for (int i = 0; i < 9; i++) {
#pragma unroll
            for (int j = i; j < 9; j++) {
                float term = g_mom[k++] * mcol[i] * mcol[j];
                e2 += (i == j) ? term : 2.0f * term;
            }
        }
        e2 /= (float)NN;
        float var = e2 - mean * mean;
        float a = rsqrtf(var + EPS) * gamma1[f];
        sA[f] = a;
        sSh[f] = beta1[f] - mean * a;
    }
    __syncthreads();

    int base = blockIdx.x * 128;
    {
        int nl = tid >> 1;
        int h = tid & 1;
        int v = base + nl;
        half2* dst = (half2*)(sZ + nl * ZLD + h * 32);
        if (v < NN) {
            float dv = g_dis[v];
            float Sv[9];
#pragma unroll
            for (int t = 0; t < 9; t++) Sv[t] = g_S[(size_t)v * 9 + t];
#pragma unroll
            for (int j = 0; j < 16; j++) {
                int f = h * 32 + 2 * j;
                float y0 = 0.f, y1 = 0.f;
#pragma unroll
                for (int t = 0; t < 9; t++) {
                    y0 = fmaf(Sv[t], sM1[t * 64 + f], y0);
                    y1 = fmaf(Sv[t], sM1[t * 64 + f + 1], y1);
                }
                float z0 = dv * fmaxf(fmaf(y0, sA[f], sSh[f]), 0.f);
                float z1 = dv * fmaxf(fmaf(y1, sA[f + 1], sSh[f + 1]), 0.f);
                dst[j] = __floats2half2_rn(z0, z1);
            }
        } else {
#pragma unroll
            for (int j = 0; j < 16; j++) dst[j] = __floats2half2_rn(0.f, 0.f);
        }
    }
    __syncthreads();

    int w = tid >> 5;
    wmma::fragment<wmma::accumulator, 16, 16, 16, float> cf[4];
#pragma unroll
    for (int n = 0; n < 4; n++) wmma::fill_fragment(cf[n], 0.0f);
#pragma unroll
    for (int k = 0; k < 4; k++) {
        wmma::fragment<wmma::matrix_a, 16, 16, 16, __half, wmma::row_major> af;
        wmma::load_matrix_sync(af, sZ + (w * 16) * ZLD + k * 16, ZLD);
#pragma unroll
        for (int n = 0; n < 4; n++) {
            wmma::fragment<wmma::matrix_b, 16, 16, 16, __half, wmma::row_major> bf;
            wmma::load_matrix_sync(bf, sW + (k * 16) * 64 + n * 16, 64);
            wmma::mma_sync(cf[n], af, bf, cf[n]);
        }
    }
#pragma unroll
    for (int n = 0; n < 4; n++) {
        wmma::fragment<wmma::accumulator, 16, 16, 16, __half> ch;
#pragma unroll
        for (int i = 0; i < cf[n].num_elements; i++) ch.x[i] = __float2half(cf[n].x[i]);
        wmma::store_matrix_sync(g_y1 + ((size_t)base + w * 16) * 64 + n * 16, ch, 64,
                                wmma::mem_row_major);
    }
}

// ======= kernel 7: CSR gather — 4 nodes/warp, MLP-4 batched row loads ========
// y[v] = dis[v] * ( y1'[v] + sum_{s in in(v)} y1'[s] )
__global__ __launch_bounds__(256) void k_gather() {
    int lane = threadIdx.x & 31;
    int sub = lane & 7;
    int grp = lane >> 3;
    int gw = (blockIdx.x * blockDim.x + threadIdx.x) >> 5;
    int nw = (gridDim.x * blockDim.x) >> 5;

    for (int v = gw * 4 + grp; v < NN; v += nw * 4) {
        // self row load issued FIRST (address known, overlaps off-loads)
        uint4 raw = ((const uint4*)(g_y1 + (size_t)v * 64))[sub];
        int off0 = __ldg(&g_off[v]), off1 = __ldg(&g_off[v + 1]);
        float a[8];
        float2 p0 = __half22float2(*(half2*)&raw.x);
        float2 p1 = __half22float2(*(half2*)&raw.y);
        float2 p2 = __half22float2(*(half2*)&raw.z);
        float2 p3 = __half22float2(*(half2*)&raw.w);
        a[0] = p0.x; a[1] = p0.y; a[2] = p1.x; a[3] = p1.y;
        a[4] = p2.x; a[5] = p2.y; a[6] = p3.x; a[7] = p3.y;

        int i = off0;
        // main loop: 4 indices, then 4 row loads, all in flight before accumulation
        for (; i + 3 < off1; i += 4) {
            int s0 = __ldg(&g_srcs[i]);
            int s1 = __ldg(&g_srcs[i + 1]);
            int s2 = __ldg(&g_srcs[i + 2]);
            int s3 = __ldg(&g_srcs[i + 3]);
            uint4 r0 = ((const uint4*)(g_y1 + (size_t)s0 * 64))[sub];
            uint4 r1 = ((const uint4*)(g_y1 + (size_t)s1 * 64))[sub];
            uint4 r2 = ((const uint4*)(g_y1 + (size_t)s2 * 64))[sub];
            uint4 r3 = ((const uint4*)(g_y1 + (size_t)s3 * 64))[sub];
            acc8(a, r0); acc8(a, r1); acc8(a, r2); acc8(a, r3);
        }
        // remainder 0..3 edges: keep 2 loads in flight where possible
        if (i + 1 < off1) {
            int s0 = __ldg(&g_srcs[i]);
            int s1 = __ldg(&g_srcs[i + 1]);
            uint4 r0 = ((const uint4*)(g_y1 + (size_t)s0 * 64))[sub];
            uint4 r1 = ((const uint4*)(g_y1 + (size_t)s1 * 64))[sub];
            acc8(a, r0); acc8(a, r1);
            i += 2;
        }
        if (i < off1) {
            int s0 = __ldg(&g_srcs[i]);
            uint4 r0 = ((const uint4*)(g_y1 + (size_t)s0 * 64))[sub];
            acc8(a, r0);
        }

        float dv = g_dis[v];
        half2 h0 = __floats2half2_rn(dv * a[0], dv * a[1]);
        half2 h1 = __floats2half2_rn(dv * a[2], dv * a[3]);
        half2 h2 = __floats2half2_rn(dv * a[4], dv * a[5]);
        half2 h3 = __floats2half2_rn(dv * a[6], dv * a[7]);
        int4 out;
        out.x = *(int*)&h0; out.y = *(int*)&h1;
        out.z = *(int*)&h2; out.w = *(int*)&h3;
        __stcs((int4*)(g_y + (size_t)v * 64) + sub, out);
    }
}

// ======= kernel 8: streaming pool + BN2 stats ================================
__global__ __launch_bounds__(256) void k_pool(const int* __restrict__ batch) {
    __shared__ float sS[8][64];
    __shared__ float sQ[8][64];
    int lane = threadIdx.x & 31;
    int wid = threadIdx.x >> 5;
    int gwarp = blockIdx.x * 8 + wid;
    int nwarps = gridDim.x * 8;
    int npw = (NN + nwarps - 1) / nwarps;
    int v0 = gwarp * npw;
    int v1 = min(v0 + npw, NN);
    int f0 = 2 * lane;

    float ps0 = 0.f, ps1 = 0.f;
    float mx0 = -__int_as_float(0x7F800000), mx1 = mx0;
    float mn0 = __int_as_float(0x7F800000), mn1 = mn0;
    float ss0 = 0.f, ss1 = 0.f, sq0 = 0.f, sq1 = 0.f;
    int gcur = -1;

    for (int v = v0; v < v1; v++) {
        unsigned int bits = __ldcs((const unsigned int*)(g_y + (size_t)v * 64) + lane);
        float2 f = __half22float2(*(half2*)&bits);
        int g = batch[v];
        if (g != gcur) {
            if (gcur >= 0) {
                int pb = gcur * 64 + f0;
                atomicAdd(&g_psum[pb], ps0);
                atomicAdd(&g_psum[pb + 1], ps1);
                atomicMaxFloat(&g_pmax[pb], mx0);
                atomicMaxFloat(&g_pmax[pb + 1], mx1);
                atomicMinFloat(&g_pmin[pb], mn0);
                atomicMinFloat(&g_pmin[pb + 1], mn1);
            }
            gcur = g;
            ps0 = 0.f; ps1 = 0.f;
            mx0 = -__int_as_float(0x7F800000); mx1 = mx0;
            mn0 = __int_as_float(0x7F800000); mn1 = mn0;
        }
        ps0 += f.x; ps1 += f.y;
        mx0 = fmaxf(mx0, f.x); mx1 = fmaxf(mx1, f.y);
        mn0 = fminf(mn0, f.x); mn1 = fminf(mn1, f.y);
        ss0 += f.x; ss1 += f.y;
        sq0 = fmaf(f.x, f.x, sq0); sq1 = fmaf(f.y, f.y, sq1);
    }
    if (gcur >= 0) {
        int pb = gcur * 64 + f0;
        atomicAdd(&g_psum[pb], ps0);
        atomicAdd(&g_psum[pb + 1], ps1);
        atomicMaxFloat(&g_pmax[pb], mx0);
        atomicMaxFloat(&g_pmax[pb + 1], mx1);
        atomicMinFloat(&g_pmin[pb], mn0);
        atomicMinFloat(&g_pmin[pb + 1], mn1);
    }
    sS[wid][f0] = ss0; sS[wid][f0 + 1] = ss1;
    sQ[wid][f0] = sq0; sQ[wid][f0 + 1] = sq1;
    __syncthreads();
    if (threadIdx.x < 64) {
        float as = 0.f, aq = 0.f;
#pragma unroll
        for (int w = 0; w < 8; w++) { as += sS[w][threadIdx.x]; aq += sQ[w][threadIdx.x]; }
        atomicAdd(&g_s2[threadIdx.x], as);
        atomicAdd(&g_q2[threadIdx.x], aq);
    }
}

// ======= kernel 9: finalize ===================================================
__global__ void k_final(const float* __restrict__ gamma2, const float* __restrict__ beta2,
                        float* __restrict__ out) {
    int f = threadIdx.x;
    if (f >= 64) return;
    float mu = g_s2[f] / (float)NN;
    float var = g_q2[f] / (float)NN - mu * mu;
    float a = rsqrtf(var + EPS) * gamma2[f];
    float sh = beta2[f] - mu * a;
    for (int g = 0; g < GG; g++) {
        float mx = __int_as_float(g_pmax[g * 64 + f]);
        float mn = __int_as_float(g_pmin[g * 64 + f]);
        float chosen = (a >= 0.f) ? mx : mn;
        out[g * 128 + f] = fmaf(chosen, a, sh);
        float c = fmaxf((float)g_cnt[g], 1.f);
        out[g * 128 + 64 + f] = fmaf(g_psum[g * 64 + f] / c, a, sh);
    }
}

// ---------------- launch ----------------
extern "C" void kernel_launch(void* const* d_in, const int* in_sizes, int n_in,
                              void* d_out, int out_size) {
    const int* node_type = (const int*)d_in[0];
    const int* num_inv   = (const int*)d_in[1];
    const int* edge      = (const int*)d_in[2];
    const int* batch     = (const int*)d_in[3];
    const float* emb_type = (const float*)d_in[4];
    const float* emb_inv  = (const float*)d_in[5];
    const float* W1       = (const float*)d_in[6];
    const float* W2       = (const float*)d_in[8];
    const float* gamma1   = (const float*)d_in[10];
    const float* beta1    = (const float*)d_in[11];
    const float* gamma2   = (const float*)d_in[12];
    const float* beta2    = (const float*)d_in[13];
    float* out = (float*)d_out;

    const int* esrc = edge;
    const int* edst = edge + EE;

    void* pDeg;
    cudaGetSymbolAddress(&pDeg, g_deg);
    cudaMemsetAsync(pDeg, 0, (size_t)NN * sizeof(int));

    k_init_deg<<<NBD + 3, 256>>>(edst, batch, emb_type, emb_inv, W1);
    k_dis_scan1<<<NBS, SCAN_B>>>(node_type, num_inv);
    k_scan23<<<NBS, SCAN_B>>>();
    k_scatter_edge1<<<NBD, 256>>>(esrc, edst);
    k_stats<<<296, 256>>>();
    k_fused1<<<(NN + 127) / 128, 256>>>(W2, gamma1, beta1);
    k_gather<<<1184, 256>>>();
    k_pool<<<296, 256>>>(batch);
    k_final<<<1, 64>>>(gamma2, beta2, out);
}